// round 4
// baseline (speedup 1.0000x reference)
#include <cuda_runtime.h>

#define NWIN  128
#define WSZ   64
#define HD    64
#define SHIFT 32
#define WTOT  8192

__device__ __forceinline__ unsigned long long pk2(float a, float b) {
    unsigned long long r;
    asm("mov.b64 %0, {%1, %2};" : "=l"(r) : "f"(a), "f"(b));
    return r;
}
__device__ __forceinline__ void upk2(unsigned long long x, float &a, float &b) {
    asm("mov.b64 {%0, %1}, %2;" : "=f"(a), "=f"(b) : "l"(x));
}
__device__ __forceinline__ void ffma2(unsigned long long &d, unsigned long long a, unsigned long long b) {
    asm("fma.rn.f32x2 %0, %1, %2, %0;" : "+l"(d) : "l"(a), "l"(b));
}

__global__ __launch_bounds__(256)
void swin_attn_kernel(const float* __restrict__ q,
                      const float* __restrict__ k,
                      const float* __restrict__ v,
                      const float* __restrict__ rel,
                      float* __restrict__ xout,
                      float* __restrict__ aout)
{
    __shared__ float Qt[WSZ * WSZ];   // Qt[kdim][row], pre-scaled by 0.125
    __shared__ float Kt[WSZ * WSZ];   // Kt[kdim][col]
    __shared__ float Vs[WSZ * WSZ];   // Vs[m][c] row-major

    const int t    = threadIdx.x;          // 0..255
    const int blk  = blockIdx.x;           // 0..B*128-1
    const int w    = blk & (NWIN - 1);
    const size_t base = (size_t)(blk >> 7) * (size_t)(WTOT * HD);
    const int wstart = w * WSZ;

    // ---- Global -> smem (roll folded into index), Q/K transposed, V straight ----
    #pragma unroll
    for (int i = 0; i < 4; i++) {
        int idx = t + i * 256;             // 0..1023 float4 slots
        int r   = idx >> 4;                // row in window 0..63
        int c4  = (idx & 15) << 2;         // col 0..60 step 4
        int g   = (wstart + r + SHIFT) & (WTOT - 1);
        size_t off = base + (size_t)g * HD + c4;
        float4 qv = *(const float4*)(q + off);
        float4 kv = *(const float4*)(k + off);
        float4 vv = *(const float4*)(v + off);
        Qt[(c4 + 0) * WSZ + r] = qv.x * 0.125f;
        Qt[(c4 + 1) * WSZ + r] = qv.y * 0.125f;
        Qt[(c4 + 2) * WSZ + r] = qv.z * 0.125f;
        Qt[(c4 + 3) * WSZ + r] = qv.w * 0.125f;
        Kt[(c4 + 0) * WSZ + r] = kv.x;
        Kt[(c4 + 1) * WSZ + r] = kv.y;
        Kt[(c4 + 2) * WSZ + r] = kv.z;
        Kt[(c4 + 3) * WSZ + r] = kv.w;
        *(float4*)(Vs + r * HD + c4) = vv;
    }

    const int tc = t & 15, tr = t >> 4;
    const int c0 = tc << 2, r0 = tr << 2;

    // Relative-position bias: this thread only ever needs n-m in [r0-c0-3, r0-c0+3]
    float bias7[7];
    {
        const int dbase = (r0 - c0) + 60;  // +63 - 3
        #pragma unroll
        for (int d = 0; d < 7; d++) bias7[d] = __ldg(rel + dbase + d);
    }

    __syncthreads();

    // ---- GEMM1: S = (Q*scale) @ K^T  (4x4 tile per thread, packed f32x2 FMA) ----
    unsigned long long acc[4][2] = {};
    #pragma unroll 8
    for (int kk = 0; kk < WSZ; kk++) {
        float4 qv = *(const float4*)(Qt + kk * WSZ + r0);
        float4 kv = *(const float4*)(Kt + kk * WSZ + c0);
        unsigned long long b01 = pk2(kv.x, kv.y);
        unsigned long long b23 = pk2(kv.z, kv.w);
        unsigned long long a0 = pk2(qv.x, qv.x);
        ffma2(acc[0][0], a0, b01); ffma2(acc[0][1], a0, b23);
        unsigned long long a1 = pk2(qv.y, qv.y);
        ffma2(acc[1][0], a1, b01); ffma2(acc[1][1], a1, b23);
        unsigned long long a2 = pk2(qv.z, qv.z);
        ffma2(acc[2][0], a2, b01); ffma2(acc[2][1], a2, b23);
        unsigned long long a3 = pk2(qv.w, qv.w);
        ffma2(acc[3][0], a3, b01); ffma2(acc[3][1], a3, b23);
    }

    float sv[4][4];
    #pragma unroll
    for (int i = 0; i < 4; i++) {
        upk2(acc[i][0], sv[i][0], sv[i][1]);
        upk2(acc[i][1], sv[i][2], sv[i][3]);
    }

    // ---- bias + shift-window mask (only last window is masked) ----
    const bool lastw = (w == NWIN - 1);
    #pragma unroll
    for (int i = 0; i < 4; i++) {
        const int n = r0 + i;
        #pragma unroll
        for (int j = 0; j < 4; j++) {
            const int m = c0 + j;
            float val = sv[i][j] + bias7[i - j + 3];
            if (lastw && ((n >= SHIFT) != (m >= SHIFT))) val -= 100.0f;
            sv[i][j] = val;
        }
    }

    // ---- softmax over each row (16 lanes per row group, lane-aligned) ----
    float inv[4];
    #pragma unroll
    for (int i = 0; i < 4; i++) {
        float mx = fmaxf(fmaxf(sv[i][0], sv[i][1]), fmaxf(sv[i][2], sv[i][3]));
        mx = fmaxf(mx, __shfl_xor_sync(0xffffffffu, mx, 1));
        mx = fmaxf(mx, __shfl_xor_sync(0xffffffffu, mx, 2));
        mx = fmaxf(mx, __shfl_xor_sync(0xffffffffu, mx, 4));
        mx = fmaxf(mx, __shfl_xor_sync(0xffffffffu, mx, 8));
        float e0 = __expf(sv[i][0] - mx);
        float e1 = __expf(sv[i][1] - mx);
        float e2 = __expf(sv[i][2] - mx);
        float e3 = __expf(sv[i][3] - mx);
        sv[i][0] = e0; sv[i][1] = e1; sv[i][2] = e2; sv[i][3] = e3;
        float sum = (e0 + e1) + (e2 + e3);
        sum += __shfl_xor_sync(0xffffffffu, sum, 1);
        sum += __shfl_xor_sync(0xffffffffu, sum, 2);
        sum += __shfl_xor_sync(0xffffffffu, sum, 4);
        sum += __shfl_xor_sync(0xffffffffu, sum, 8);
        inv[i] = __fdividef(1.0f, sum);
    }

    // ---- write attn (global) + P^T into smem (reuse Qt) ----
    __syncthreads();                      // everyone done reading Qt/Kt
    float* Pt = Qt;                       // Pt[m][n]
    const size_t aoff = (size_t)blk * (WSZ * WSZ);
    #pragma unroll
    for (int i = 0; i < 4; i++) {
        float p0 = sv[i][0] * inv[i];
        float p1 = sv[i][1] * inv[i];
        float p2 = sv[i][2] * inv[i];
        float p3 = sv[i][3] * inv[i];
        Pt[(c0 + 0) * WSZ + (r0 + i)] = p0;
        Pt[(c0 + 1) * WSZ + (r0 + i)] = p1;
        Pt[(c0 + 2) * WSZ + (r0 + i)] = p2;
        Pt[(c0 + 3) * WSZ + (r0 + i)] = p3;
        *(float4*)(aout + aoff + (size_t)(r0 + i) * WSZ + c0) = make_float4(p0, p1, p2, p3);
    }
    __syncthreads();

    // ---- GEMM2: O = P @ V ----
    unsigned long long oacc[4][2] = {};
    #pragma unroll 8
    for (int m = 0; m < WSZ; m++) {
        float4 pv = *(const float4*)(Pt + m * WSZ + r0);
        float4 vv = *(const float4*)(Vs + m * HD + c0);
        unsigned long long b01 = pk2(vv.x, vv.y);
        unsigned long long b23 = pk2(vv.z, vv.w);
        unsigned long long a0 = pk2(pv.x, pv.x);
        ffma2(oacc[0][0], a0, b01); ffma2(oacc[0][1], a0, b23);
        unsigned long long a1 = pk2(pv.y, pv.y);
        ffma2(oacc[1][0], a1, b01); ffma2(oacc[1][1], a1, b23);
        unsigned long long a2 = pk2(pv.z, pv.z);
        ffma2(oacc[2][0], a2, b01); ffma2(oacc[2][1], a2, b23);
        unsigned long long a3 = pk2(pv.w, pv.w);
        ffma2(oacc[3][0], a3, b01); ffma2(oacc[3][1], a3, b23);
    }

    #pragma unroll
    for (int i = 0; i < 4; i++) {
        float o0, o1, o2, o3;
        upk2(oacc[i][0], o0, o1);
        upk2(oacc[i][1], o2, o3);
        int g = (wstart + r0 + i + SHIFT) & (WTOT - 1);   // inverse roll == same map
        *(float4*)(xout + base + (size_t)g * HD + c0) = make_float4(o0, o1, o2, o3);
    }
}

extern "C" void kernel_launch(void* const* d_in, const int* in_sizes, int n_in,
                              void* d_out, int out_size) {
    const float* q   = (const float*)d_in[0];
    const float* k   = (const float*)d_in[1];
    const float* v   = (const float*)d_in[2];
    const float* rel = (const float*)d_in[3];

    const int B = in_sizes[0] / (WTOT * HD);      // 32
    float* xout = (float*)d_out;
    float* aout = xout + (size_t)B * WTOT * HD;   // attn follows x

    swin_attn_kernel<<<B * NWIN, 256>>>(q, k, v, rel, xout, aout);
}

// round 5
// speedup vs baseline: 1.3008x; 1.3008x over previous
#include <cuda_runtime.h>

#define WSZ 64
#define HD 64
#define SHIFT 32
#define WTOT 8192
#define NWIN 128

typedef unsigned long long u64;
__device__ __forceinline__ u64 pk2(float a, float b) {
    u64 r; asm("mov.b64 %0, {%1, %2};" : "=l"(r) : "f"(a), "f"(b)); return r;
}
__device__ __forceinline__ void upk2(u64 x, float &a, float &b) {
    asm("mov.b64 {%0, %1}, %2;" : "=f"(a), "=f"(b) : "l"(x));
}
__device__ __forceinline__ void ffma2(u64 &d, u64 a, u64 b) {
    asm("fma.rn.f32x2 %0, %1, %2, %0;" : "+l"(d) : "l"(a), "l"(b));
}
// swizzled index into [64][64] transposed tiles; keeps 16B alignment
__device__ __forceinline__ int SW(int row, int f) {
    return (row << 6) + (f ^ ((row & 7) << 2));
}

__global__ __launch_bounds__(64)
void swin_attn8(const float* __restrict__ q, const float* __restrict__ k,
                const float* __restrict__ v, const float* __restrict__ rel,
                float* __restrict__ xout, float* __restrict__ aout)
{
    __shared__ float Qt[WSZ * WSZ];   // [kdim][row] swizzled; later Pt[m][row]
    __shared__ float Kt[WSZ * WSZ];   // [kdim][col] swizzled
    __shared__ float Vs[WSZ * WSZ];   // [m][col] linear

    const int t = threadIdx.x, blk = blockIdx.x;
    const int w = blk & (NWIN - 1);
    const size_t base = (size_t)(blk >> 7) * (size_t)(WTOT * HD);
    const int wstart = w * WSZ;
    const int rb = t >> 3, c4 = (t & 7) << 2, rot = (t >> 1) & 3;

    // ---- load: Q/K transposed+swizzled (roll folded into row index), V linear
    #pragma unroll
    for (int i = 0; i < 8; i++) {
        int r = rb + 8 * i;
        int g = (wstart + r + SHIFT) & (WTOT - 1);
        size_t off = base + (size_t)g * HD + c4;
        #pragma unroll
        for (int h = 0; h < 2; h++) {
            float4 qv = *(const float4*)(q + off + 32 * h);
            float4 kv = *(const float4*)(k + off + 32 * h);
            float4 vv = *(const float4*)(v + off + 32 * h);
            float qa[4] = {qv.x * 0.125f, qv.y * 0.125f, qv.z * 0.125f, qv.w * 0.125f};
            float ka[4] = {kv.x, kv.y, kv.z, kv.w};
            #pragma unroll
            for (int jj = 0; jj < 4; jj++) {
                int jr = (jj + rot) & 3;              // rotation -> conflict-free
                Qt[SW(c4 + 32 * h + jr, r)] = qa[jr];
                Kt[SW(c4 + 32 * h + jr, r)] = ka[jr];
            }
            *(float4*)(Vs + r * HD + c4 + 32 * h) = vv;
        }
    }
    __syncthreads();

    const int r0 = rb << 3, c0 = c4;

    // ---- GEMM1: S = (Q*scale) @ K^T, 8 rows x 8 cols per thread
    u64 acc[8][4];
    #pragma unroll
    for (int j = 0; j < 8; j++) { acc[j][0]=acc[j][1]=acc[j][2]=acc[j][3]=0ull; }
    #pragma unroll 4
    for (int kk = 0; kk < WSZ; kk++) {
        float4 k0 = *(const float4*)(Kt + SW(kk, c0));
        float4 k1 = *(const float4*)(Kt + SW(kk, c0 + 32));
        ulonglong2 qA = *(const ulonglong2*)(Qt + SW(kk, r0));
        ulonglong2 qB = *(const ulonglong2*)(Qt + SW(kk, r0 + 4));
        u64 qp[4] = {qA.x, qA.y, qB.x, qB.y};
        u64 kd[8] = {pk2(k0.x,k0.x), pk2(k0.y,k0.y), pk2(k0.z,k0.z), pk2(k0.w,k0.w),
                     pk2(k1.x,k1.x), pk2(k1.y,k1.y), pk2(k1.z,k1.z), pk2(k1.w,k1.w)};
        #pragma unroll
        for (int j = 0; j < 8; j++)
            #pragma unroll
            for (int p = 0; p < 4; p++) ffma2(acc[j][p], qp[p], kd[j]);
    }
    float sv[8][8];
    #pragma unroll
    for (int j = 0; j < 8; j++)
        #pragma unroll
        for (int p = 0; p < 4; p++) upk2(acc[j][p], sv[2*p][j], sv[2*p+1][j]);

    // ---- bias + shift mask
    const int dbA = r0 - c0 + 60, dbB = dbA - 32;
    float bA[11], bB[11];
    #pragma unroll
    for (int d = 0; d < 11; d++) { bA[d] = __ldg(rel + dbA + d); bB[d] = __ldg(rel + dbB + d); }
    const bool lastw = (w == NWIN - 1);
    const float m0 = (lastw && rb >= 4) ? -100.0f : 0.0f;
    const float m1 = (lastw && rb <  4) ? -100.0f : 0.0f;
    #pragma unroll
    for (int i = 0; i < 8; i++)
        #pragma unroll
        for (int d = 0; d < 4; d++) {
            sv[i][d]     += bA[i - d + 3] + m0;
            sv[i][d + 4] += bB[i - d + 3] + m1;
        }

    // ---- softmax per row (8 cols in-thread, xor-shuffle over 8-lane row group)
    #pragma unroll
    for (int i = 0; i < 8; i++) {
        float mx = sv[i][0];
        #pragma unroll
        for (int j = 1; j < 8; j++) mx = fmaxf(mx, sv[i][j]);
        mx = fmaxf(mx, __shfl_xor_sync(~0u, mx, 1));
        mx = fmaxf(mx, __shfl_xor_sync(~0u, mx, 2));
        mx = fmaxf(mx, __shfl_xor_sync(~0u, mx, 4));
        float sum = 0.f;
        #pragma unroll
        for (int j = 0; j < 8; j++) { sv[i][j] = __expf(sv[i][j] - mx); sum += sv[i][j]; }
        sum += __shfl_xor_sync(~0u, sum, 1);
        sum += __shfl_xor_sync(~0u, sum, 2);
        sum += __shfl_xor_sync(~0u, sum, 4);
        float inv = __fdividef(1.f, sum);
        #pragma unroll
        for (int j = 0; j < 8; j++) sv[i][j] *= inv;
    }

    // ---- attn store + P^T into Qt (swizzled, rotated)
    const size_t aoff = (size_t)blk * (WSZ * WSZ);
    #pragma unroll
    for (int i = 0; i < 8; i++) {
        *(float4*)(aout + aoff + (size_t)(r0+i)*WSZ + c0)      = make_float4(sv[i][0],sv[i][1],sv[i][2],sv[i][3]);
        *(float4*)(aout + aoff + (size_t)(r0+i)*WSZ + c0 + 32) = make_float4(sv[i][4],sv[i][5],sv[i][6],sv[i][7]);
    }
    __syncthreads();                      // all GEMM1 reads of Qt done
    #pragma unroll
    for (int h = 0; h < 2; h++)
        #pragma unroll
        for (int d = 0; d < 4; d++) {
            int dr = (d + rot) & 3;
            int j = dr + 4 * h, c = c0 + 32 * h + dr;
            *(float4*)(Qt + SW(c, r0))     = make_float4(sv[0][j], sv[1][j], sv[2][j], sv[3][j]);
            *(float4*)(Qt + SW(c, r0 + 4)) = make_float4(sv[4][j], sv[5][j], sv[6][j], sv[7][j]);
        }
    __syncthreads();

    // ---- GEMM2: O = P @ V
    u64 oa[8][4];
    #pragma unroll
    for (int j = 0; j < 8; j++) { oa[j][0]=oa[j][1]=oa[j][2]=oa[j][3]=0ull; }
    #pragma unroll 4
    for (int m = 0; m < WSZ; m++) {
        float4 v0 = *(const float4*)(Vs + m * HD + c0);
        float4 v1 = *(const float4*)(Vs + m * HD + c0 + 32);
        ulonglong2 pA = *(const ulonglong2*)(Qt + SW(m, r0));
        ulonglong2 pB = *(const ulonglong2*)(Qt + SW(m, r0 + 4));
        u64 pp[4] = {pA.x, pA.y, pB.x, pB.y};
        u64 vd[8] = {pk2(v0.x,v0.x), pk2(v0.y,v0.y), pk2(v0.z,v0.z), pk2(v0.w,v0.w),
                     pk2(v1.x,v1.x), pk2(v1.y,v1.y), pk2(v1.z,v1.z), pk2(v1.w,v1.w)};
        #pragma unroll
        for (int j = 0; j < 8; j++)
            #pragma unroll
            for (int p = 0; p < 4; p++) ffma2(oa[j][p], pp[p], vd[j]);
    }

    // ---- output store (roll folded back in)
    #pragma unroll
    for (int p = 0; p < 4; p++) {
        float o[2][8];
        #pragma unroll
        for (int j = 0; j < 8; j++) upk2(oa[j][p], o[0][j], o[1][j]);
        #pragma unroll
        for (int s = 0; s < 2; s++) {
            int g = (wstart + r0 + 2*p + s + SHIFT) & (WTOT - 1);
            *(float4*)(xout + base + (size_t)g*HD + c0)      = make_float4(o[s][0],o[s][1],o[s][2],o[s][3]);
            *(float4*)(xout + base + (size_t)g*HD + c0 + 32) = make_float4(o[s][4],o[s][5],o[s][6],o[s][7]);
        }
    }
}

extern "C" void kernel_launch(void* const* d_in, const int* in_sizes, int n_in,
                              void* d_out, int out_size) {
    const float* q   = (const float*)d_in[0];
    const float* k   = (const float*)d_in[1];
    const float* v   = (const float*)d_in[2];
    const float* rel = (const float*)d_in[3];
    const int B = in_sizes[0] / (WTOT * HD);
    float* xout = (float*)d_out;
    float* aout = xout + (size_t)B * WTOT * HD;
    swin_attn8<<<B * NWIN, 64>>>(q, k, v, rel, xout, aout);
}